// round 4
// baseline (speedup 1.0000x reference)
#include <cuda_runtime.h>
#include <math.h>

// Problem constants (B=128, N=511, M=256, R=64, IN=512)
#define BATCH  128
#define NNODES 511
#define MDIM   256
#define RDIM   64
#define INDIM  512

// GEMM tiling: block tile 128 rows x 64 cols, thread tile 8 rows x 4 cols x NACC gates
#define BM 128
#define BN 64
#define BK 16
#define SAS8 132    // padded sA row stride (words); 132*4B mult of 16 -> LDS.128 aligned
#define NTH 256

typedef unsigned long long ull;

// Persistent scratch (device globals; no allocation)
__device__ float g_h_buf[(size_t)NNODES * BATCH * MDIM];   // [node][b][m]
__device__ float g_c_buf[(size_t)NNODES * BATCH * MDIM];
__device__ float g_h1[(size_t)128 * BATCH * MDIM];         // cell1 h
__device__ float g_c1[(size_t)128 * BATCH * MDIM];         // cell1 c
__device__ float g_ht[(size_t)128 * BATCH * MDIM];         // h_tilde
__device__ float g_ig[(size_t)128 * BATCH * MDIM];         // cell2 sig(i)*tanh(g)
__device__ float g_iu[(size_t)128 * BATCH * MDIM];         // gates sig(i)*tanh(u)
__device__ float g_og[(size_t)128 * BATCH * MDIM];         // gates sig(o)
__device__ float g_fx[(size_t)128 * BATCH * MDIM];         // gates fx pre-activation

__device__ __forceinline__ float sigf(float x) { return 1.0f / (1.0f + expf(-x)); }

// ---- packed f32x2 helpers (sm_103a FFMA2) ----
__device__ __forceinline__ ull pack2(float x) {
    ull r;
    unsigned u = __float_as_uint(x);
    asm("mov.b64 %0, {%1, %1};" : "=l"(r) : "r"(u));
    return r;
}
__device__ __forceinline__ void ffma2(ull& d, ull a, ull b) {
    asm("fma.rn.f32x2 %0, %1, %2, %0;" : "+l"(d) : "l"(a), "l"(b));
}
__device__ __forceinline__ void unp2(ull v, float& lo, float& hi) {
    unsigned l, h;
    asm("mov.b64 {%0, %1}, %2;" : "=r"(l), "=r"(h) : "l"(v));
    lo = __uint_as_float(l);
    hi = __uint_as_float(h);
}
__device__ __forceinline__ void unp4(const ull* a2, float* v) {
    unp2(a2[0], v[0], v[1]);
    unp2(a2[1], v[2], v[3]);
}

// 8-row x 4-col x NACC tiled GEMM phase. Double-buffered smem, 1 sync/step,
// register prefetch. acc[j][r][p]: row r (of 8), packed col pair p.
template<int NACC>
__device__ __forceinline__ void gemm8(
    ull (*acc)[8][2],
    const float* const* rowptr,
    const float* const (&Bp)[NACC],
    int ldb, int K,
    float* sA, float* sB, int tid)
{
    const int ty = tid >> 4, tx = tid & 15;
    const int ar = tid >> 1, akv = (tid & 1) * 8;
    const int bk = tid >> 4, bnv = (tid & 15) * 4;
    const float* aptr = rowptr[ar];
    const int ASZ = BK * SAS8;
    const int BSZ = NACC * BK * BN;

    float4 av0 = *reinterpret_cast<const float4*>(aptr + akv);
    float4 av1 = *reinterpret_cast<const float4*>(aptr + akv + 4);
    float4 bv[NACC];
#pragma unroll
    for (int j = 0; j < NACC; j++)
        bv[j] = *reinterpret_cast<const float4*>(Bp[j] + (size_t)bk * ldb + bnv);

    sA[(akv + 0) * SAS8 + ar] = av0.x;
    sA[(akv + 1) * SAS8 + ar] = av0.y;
    sA[(akv + 2) * SAS8 + ar] = av0.z;
    sA[(akv + 3) * SAS8 + ar] = av0.w;
    sA[(akv + 4) * SAS8 + ar] = av1.x;
    sA[(akv + 5) * SAS8 + ar] = av1.y;
    sA[(akv + 6) * SAS8 + ar] = av1.z;
    sA[(akv + 7) * SAS8 + ar] = av1.w;
#pragma unroll
    for (int j = 0; j < NACC; j++)
        *reinterpret_cast<float4*>(&sB[(j * BK + bk) * BN + bnv]) = bv[j];
    __syncthreads();

    int cur = 0;
    for (int k0 = 0; k0 < K; k0 += BK) {
        const bool more = (k0 + BK) < K;
        if (more) {
            av0 = *reinterpret_cast<const float4*>(aptr + k0 + BK + akv);
            av1 = *reinterpret_cast<const float4*>(aptr + k0 + BK + akv + 4);
#pragma unroll
            for (int j = 0; j < NACC; j++)
                bv[j] = *reinterpret_cast<const float4*>(Bp[j] + (size_t)(k0 + BK + bk) * ldb + bnv);
        }
        const float* cA = sA + cur * ASZ;
        const float* cB = sB + cur * BSZ;
#pragma unroll
        for (int kk = 0; kk < BK; kk++) {
            float4 alo = *reinterpret_cast<const float4*>(cA + kk * SAS8 + ty * 8);
            float4 ahi = *reinterpret_cast<const float4*>(cA + kk * SAS8 + ty * 8 + 4);
            ull a[8];
            a[0] = pack2(alo.x); a[1] = pack2(alo.y); a[2] = pack2(alo.z); a[3] = pack2(alo.w);
            a[4] = pack2(ahi.x); a[5] = pack2(ahi.y); a[6] = pack2(ahi.z); a[7] = pack2(ahi.w);
#pragma unroll
            for (int j = 0; j < NACC; j++) {
                ulonglong2 b = *reinterpret_cast<const ulonglong2*>(cB + (j * BK + kk) * BN + tx * 4);
#pragma unroll
                for (int r = 0; r < 8; r++) {
                    ffma2(acc[j][r][0], a[r], b.x);
                    ffma2(acc[j][r][1], a[r], b.y);
                }
            }
        }
        if (more) {
            const int nxt = cur ^ 1;
            float* nA = sA + nxt * ASZ;
            float* nB = sB + nxt * BSZ;
            nA[(akv + 0) * SAS8 + ar] = av0.x;
            nA[(akv + 1) * SAS8 + ar] = av0.y;
            nA[(akv + 2) * SAS8 + ar] = av0.z;
            nA[(akv + 3) * SAS8 + ar] = av0.w;
            nA[(akv + 4) * SAS8 + ar] = av1.x;
            nA[(akv + 5) * SAS8 + ar] = av1.y;
            nA[(akv + 6) * SAS8 + ar] = av1.z;
            nA[(akv + 7) * SAS8 + ar] = av1.w;
#pragma unroll
            for (int j = 0; j < NACC; j++)
                *reinterpret_cast<float4*>(&nB[(j * BK + bk) * BN + bnv]) = bv[j];
            __syncthreads();
            cur = nxt;
        }
    }
}

// Dual-A variant: two A sources share one B. acc[0] <- A0*B, acc[1] <- A1*B.
__device__ __forceinline__ void gemm8_dual(
    ull (*acc)[8][2],
    const float* const* rp0, const float* const* rp1,
    const float* Bp, int ldb, int K,
    float* sA0, float* sA1, float* sB, int tid)
{
    const int ty = tid >> 4, tx = tid & 15;
    const int ar = tid >> 1, akv = (tid & 1) * 8;
    const int bk = tid >> 4, bnv = (tid & 15) * 4;
    const float* ap0 = rp0[ar];
    const float* ap1 = rp1[ar];
    const int ASZ = BK * SAS8;
    const int BSZ = BK * BN;

    float4 p00 = *reinterpret_cast<const float4*>(ap0 + akv);
    float4 p01 = *reinterpret_cast<const float4*>(ap0 + akv + 4);
    float4 p10 = *reinterpret_cast<const float4*>(ap1 + akv);
    float4 p11 = *reinterpret_cast<const float4*>(ap1 + akv + 4);
    float4 bv = *reinterpret_cast<const float4*>(Bp + (size_t)bk * ldb + bnv);

#pragma unroll
    for (int j = 0; j < 4; j++) {
        sA0[(akv + j) * SAS8 + ar]     = (&p00.x)[j];
        sA0[(akv + 4 + j) * SAS8 + ar] = (&p01.x)[j];
        sA1[(akv + j) * SAS8 + ar]     = (&p10.x)[j];
        sA1[(akv + 4 + j) * SAS8 + ar] = (&p11.x)[j];
    }
    *reinterpret_cast<float4*>(&sB[bk * BN + bnv]) = bv;
    __syncthreads();

    int cur = 0;
    for (int k0 = 0; k0 < K; k0 += BK) {
        const bool more = (k0 + BK) < K;
        if (more) {
            p00 = *reinterpret_cast<const float4*>(ap0 + k0 + BK + akv);
            p01 = *reinterpret_cast<const float4*>(ap0 + k0 + BK + akv + 4);
            p10 = *reinterpret_cast<const float4*>(ap1 + k0 + BK + akv);
            p11 = *reinterpret_cast<const float4*>(ap1 + k0 + BK + akv + 4);
            bv  = *reinterpret_cast<const float4*>(Bp + (size_t)(k0 + BK + bk) * ldb + bnv);
        }
        const float* cA0 = sA0 + cur * ASZ;
        const float* cA1 = sA1 + cur * ASZ;
        const float* cB = sB + cur * BSZ;
#pragma unroll
        for (int kk = 0; kk < BK; kk++) {
            float4 l0 = *reinterpret_cast<const float4*>(cA0 + kk * SAS8 + ty * 8);
            float4 h0 = *reinterpret_cast<const float4*>(cA0 + kk * SAS8 + ty * 8 + 4);
            float4 l1 = *reinterpret_cast<const float4*>(cA1 + kk * SAS8 + ty * 8);
            float4 h1 = *reinterpret_cast<const float4*>(cA1 + kk * SAS8 + ty * 8 + 4);
            ulonglong2 b = *reinterpret_cast<const ulonglong2*>(cB + kk * BN + tx * 4);
            ull a;
#pragma unroll
            for (int r = 0; r < 4; r++) {
                a = pack2((&l0.x)[r]);
                ffma2(acc[0][r][0], a, b.x); ffma2(acc[0][r][1], a, b.y);
                a = pack2((&h0.x)[r]);
                ffma2(acc[0][4 + r][0], a, b.x); ffma2(acc[0][4 + r][1], a, b.y);
                a = pack2((&l1.x)[r]);
                ffma2(acc[1][r][0], a, b.x); ffma2(acc[1][r][1], a, b.y);
                a = pack2((&h1.x)[r]);
                ffma2(acc[1][4 + r][0], a, b.x); ffma2(acc[1][4 + r][1], a, b.y);
            }
        }
        if (more) {
            const int nxt = cur ^ 1;
            float* nA0 = sA0 + nxt * ASZ;
            float* nA1 = sA1 + nxt * ASZ;
            float* nB = sB + nxt * BSZ;
#pragma unroll
            for (int j = 0; j < 4; j++) {
                nA0[(akv + j) * SAS8 + ar]     = (&p00.x)[j];
                nA0[(akv + 4 + j) * SAS8 + ar] = (&p01.x)[j];
                nA1[(akv + j) * SAS8 + ar]     = (&p10.x)[j];
                nA1[(akv + 4 + j) * SAS8 + ar] = (&p11.x)[j];
            }
            *reinterpret_cast<float4*>(&nB[bk * BN + bnv]) = bv;
            __syncthreads();
            cur = nxt;
        }
    }
}

// ======================= Leaf =======================
__global__ void __launch_bounds__(NTH, 2)
k_leaf_iu(const float* __restrict__ wte,
          const float* __restrict__ Wix, const float* __restrict__ Wux,
          const float* __restrict__ bix, const float* __restrict__ bih,
          const float* __restrict__ bux, const float* __restrict__ buh)
{
    __shared__ __align__(16) float sA[2 * BK * SAS8];
    __shared__ __align__(16) float sB[2 * 2 * BK * BN];
    __shared__ const float* rowptr[BM];
    const int tid = threadIdx.x;
    const int rb = blockIdx.x * BM;
    const int n0 = blockIdx.y * BN;

    ull acc[2][8][2];
#pragma unroll
    for (int j = 0; j < 2; j++)
#pragma unroll
        for (int r = 0; r < 8; r++) { acc[j][r][0] = 0ull; acc[j][r][1] = 0ull; }

    if (tid < BM) {
        int r = rb + tid;
        int node = 255 + (r >> 7);
        int b = r & 127;
        rowptr[tid] = wte + (size_t)(b * NNODES + node) * INDIM;
    }
    __syncthreads();
    {
        const float* const Bp[2] = { Wix + n0, Wux + n0 };
        gemm8<2>(acc, rowptr, Bp, MDIM, INDIM, sA, sB, tid);
    }
    const int ty = tid >> 4, tx = tid & 15;
    const int m0 = n0 + tx * 4;
#pragma unroll
    for (int r8 = 0; r8 < 8; r8++) {
        int r = rb + ty * 8 + r8;
        int node = 255 + (r >> 7);
        int b = r & 127;
        size_t base = (size_t)(node * BATCH + b) * MDIM + m0;
        float vi[4], vu[4];
        unp4(acc[0][r8], vi);
        unp4(acc[1][r8], vu);
        float4 cv;
#pragma unroll
        for (int q = 0; q < 4; q++) {
            int m = m0 + q;
            (&cv.x)[q] = sigf(vi[q] + bix[m] + bih[m]) * tanhf(vu[q] + bux[m] + buh[m]);
        }
        *reinterpret_cast<float4*>(&g_c_buf[base]) = cv;
    }
}

__global__ void __launch_bounds__(NTH, 2)
k_leaf_o(const float* __restrict__ wte,
         const float* __restrict__ Wox,
         const float* __restrict__ boxb, const float* __restrict__ boh)
{
    __shared__ __align__(16) float sA[2 * BK * SAS8];
    __shared__ __align__(16) float sB[2 * 1 * BK * BN];
    __shared__ const float* rowptr[BM];
    const int tid = threadIdx.x;
    const int rb = blockIdx.x * BM;
    const int n0 = blockIdx.y * BN;

    ull acc[1][8][2];
#pragma unroll
    for (int r = 0; r < 8; r++) { acc[0][r][0] = 0ull; acc[0][r][1] = 0ull; }

    if (tid < BM) {
        int r = rb + tid;
        int node = 255 + (r >> 7);
        int b = r & 127;
        rowptr[tid] = wte + (size_t)(b * NNODES + node) * INDIM;
    }
    __syncthreads();
    {
        const float* const Bp[1] = { Wox + n0 };
        gemm8<1>(acc, rowptr, Bp, MDIM, INDIM, sA, sB, tid);
    }
    const int ty = tid >> 4, tx = tid & 15;
    const int m0 = n0 + tx * 4;
#pragma unroll
    for (int r8 = 0; r8 < 8; r8++) {
        int r = rb + ty * 8 + r8;
        int node = 255 + (r >> 7);
        int b = r & 127;
        size_t base = (size_t)(node * BATCH + b) * MDIM + m0;
        float vo[4];
        unp4(acc[0][r8], vo);
        float4 cv = *reinterpret_cast<const float4*>(&g_c_buf[base]);
        float4 hv;
#pragma unroll
        for (int q = 0; q < 4; q++) {
            int m = m0 + q;
            (&hv.x)[q] = sigf(vo[q] + boxb[m] + boh[m]) * tanhf((&cv.x)[q]);
        }
        *reinterpret_cast<float4*>(&g_h_buf[base]) = hv;
    }
}

// ======================= Cell 1 (child 2n+1, h=c=0) =======================
__global__ void __launch_bounds__(NTH, 2)
k_cell1_ig(const float* __restrict__ rel,
           const float* __restrict__ Wsih,
           const float* __restrict__ bsi, const float* __restrict__ bsh,
           int nodeBase)
{
    __shared__ __align__(16) float sA[2 * BK * SAS8];
    __shared__ __align__(16) float sB[2 * 2 * BK * BN];
    __shared__ const float* rowptr[BM];
    const int tid = threadIdx.x;
    const int rb = blockIdx.x * BM;
    const int n0 = blockIdx.y * BN;

    ull acc[2][8][2];
#pragma unroll
    for (int j = 0; j < 2; j++)
#pragma unroll
        for (int r = 0; r < 8; r++) { acc[j][r][0] = 0ull; acc[j][r][1] = 0ull; }

    if (tid < BM) {
        int r = rb + tid;
        int node = nodeBase + (r >> 7);
        int b = r & 127;
        rowptr[tid] = g_h_buf + (size_t)((2 * node + 1) * BATCH + b) * MDIM;
    }
    __syncthreads();
    {
        const float* const Bp[2] = { Wsih + n0, Wsih + 512 + n0 };
        gemm8<2>(acc, rowptr, Bp, 1024, MDIM, sA, sB, tid);
    }
    __syncthreads();
    if (tid < BM) {
        int r = rb + tid;
        int node = nodeBase + (r >> 7);
        int b = r & 127;
        rowptr[tid] = rel + (size_t)(b * NNODES + 2 * node + 1) * RDIM;
    }
    __syncthreads();
    {
        const float* const Bp[2] = { Wsih + 256 * 1024 + n0, Wsih + 256 * 1024 + 512 + n0 };
        gemm8<2>(acc, rowptr, Bp, 1024, RDIM, sA, sB, tid);
    }
    const int ty = tid >> 4, tx = tid & 15;
    const int m0 = n0 + tx * 4;
#pragma unroll
    for (int r8 = 0; r8 < 8; r8++) {
        int r = rb + ty * 8 + r8;
        size_t base = (size_t)r * MDIM + m0;
        float vi[4], vg[4];
        unp4(acc[0][r8], vi);
        unp4(acc[1][r8], vg);
        float4 cv;
#pragma unroll
        for (int q = 0; q < 4; q++) {
            int m = m0 + q;
            (&cv.x)[q] = sigf(vi[q] + bsi[m] + bsh[m]) * tanhf(vg[q] + bsi[512 + m] + bsh[512 + m]);
        }
        *reinterpret_cast<float4*>(&g_c1[base]) = cv;
    }
}

__global__ void __launch_bounds__(NTH, 2)
k_cell1_o(const float* __restrict__ rel,
          const float* __restrict__ Wsih,
          const float* __restrict__ bsi, const float* __restrict__ bsh,
          int nodeBase)
{
    __shared__ __align__(16) float sA[2 * BK * SAS8];
    __shared__ __align__(16) float sB[2 * 1 * BK * BN];
    __shared__ const float* rowptr[BM];
    const int tid = threadIdx.x;
    const int rb = blockIdx.x * BM;
    const int n0 = blockIdx.y * BN;

    ull acc[1][8][2];
#pragma unroll
    for (int r = 0; r < 8; r++) { acc[0][r][0] = 0ull; acc[0][r][1] = 0ull; }

    if (tid < BM) {
        int r = rb + tid;
        int node = nodeBase + (r >> 7);
        int b = r & 127;
        rowptr[tid] = g_h_buf + (size_t)((2 * node + 1) * BATCH + b) * MDIM;
    }
    __syncthreads();
    {
        const float* const Bp[1] = { Wsih + 768 + n0 };
        gemm8<1>(acc, rowptr, Bp, 1024, MDIM, sA, sB, tid);
    }
    __syncthreads();
    if (tid < BM) {
        int r = rb + tid;
        int node = nodeBase + (r >> 7);
        int b = r & 127;
        rowptr[tid] = rel + (size_t)(b * NNODES + 2 * node + 1) * RDIM;
    }
    __syncthreads();
    {
        const float* const Bp[1] = { Wsih + 256 * 1024 + 768 + n0 };
        gemm8<1>(acc, rowptr, Bp, 1024, RDIM, sA, sB, tid);
    }
    const int ty = tid >> 4, tx = tid & 15;
    const int m0 = n0 + tx * 4;
#pragma unroll
    for (int r8 = 0; r8 < 8; r8++) {
        int r = rb + ty * 8 + r8;
        size_t base = (size_t)r * MDIM + m0;
        float vo[4];
        unp4(acc[0][r8], vo);
        float4 cv = *reinterpret_cast<const float4*>(&g_c1[base]);
        float4 hv;
#pragma unroll
        for (int q = 0; q < 4; q++) {
            int m = m0 + q;
            (&hv.x)[q] = sigf(vo[q] + bsi[768 + m] + bsh[768 + m]) * tanhf((&cv.x)[q]);
        }
        *reinterpret_cast<float4*>(&g_h1[base]) = hv;
    }
}

// ======================= Cell 2 (child 2n+2, state = cell1) =======================
__global__ void __launch_bounds__(NTH, 2)
k_cell2_ig(const float* __restrict__ rel,
           const float* __restrict__ Wsih, const float* __restrict__ Wshh,
           const float* __restrict__ bsi, const float* __restrict__ bsh,
           int nodeBase)
{
    __shared__ __align__(16) float sA[2 * BK * SAS8];
    __shared__ __align__(16) float sB[2 * 2 * BK * BN];
    __shared__ const float* rowptr[BM];
    const int tid = threadIdx.x;
    const int rb = blockIdx.x * BM;
    const int n0 = blockIdx.y * BN;

    ull acc[2][8][2];
#pragma unroll
    for (int j = 0; j < 2; j++)
#pragma unroll
        for (int r = 0; r < 8; r++) { acc[j][r][0] = 0ull; acc[j][r][1] = 0ull; }

    if (tid < BM) {
        int r = rb + tid;
        int node = nodeBase + (r >> 7);
        int b = r & 127;
        rowptr[tid] = g_h_buf + (size_t)((2 * node + 2) * BATCH + b) * MDIM;
    }
    __syncthreads();
    {
        const float* const Bp[2] = { Wsih + n0, Wsih + 512 + n0 };
        gemm8<2>(acc, rowptr, Bp, 1024, MDIM, sA, sB, tid);
    }
    __syncthreads();
    if (tid < BM) {
        int r = rb + tid;
        int node = nodeBase + (r >> 7);
        int b = r & 127;
        rowptr[tid] = rel + (size_t)(b * NNODES + 2 * node + 2) * RDIM;
    }
    __syncthreads();
    {
        const float* const Bp[2] = { Wsih + 256 * 1024 + n0, Wsih + 256 * 1024 + 512 + n0 };
        gemm8<2>(acc, rowptr, Bp, 1024, RDIM, sA, sB, tid);
    }
    __syncthreads();
    if (tid < BM) {
        int r = rb + tid;
        rowptr[tid] = g_h1 + (size_t)r * MDIM;
    }
    __syncthreads();
    {
        const float* const Bp[2] = { Wshh + n0, Wshh + 512 + n0 };
        gemm8<2>(acc, rowptr, Bp, 1024, MDIM, sA, sB, tid);
    }
    const int ty = tid >> 4, tx = tid & 15;
    const int m0 = n0 + tx * 4;
#pragma unroll
    for (int r8 = 0; r8 < 8; r8++) {
        int r = rb + ty * 8 + r8;
        size_t base = (size_t)r * MDIM + m0;
        float vi[4], vg[4];
        unp4(acc[0][r8], vi);
        unp4(acc[1][r8], vg);
        float4 cv;
#pragma unroll
        for (int q = 0; q < 4; q++) {
            int m = m0 + q;
            (&cv.x)[q] = sigf(vi[q] + bsi[m] + bsh[m]) * tanhf(vg[q] + bsi[512 + m] + bsh[512 + m]);
        }
        *reinterpret_cast<float4*>(&g_ig[base]) = cv;
    }
}

__global__ void __launch_bounds__(NTH, 2)
k_cell2_fo(const float* __restrict__ rel,
           const float* __restrict__ Wsih, const float* __restrict__ Wshh,
           const float* __restrict__ bsi, const float* __restrict__ bsh,
           int nodeBase)
{
    __shared__ __align__(16) float sA[2 * BK * SAS8];
    __shared__ __align__(16) float sB[2 * 2 * BK * BN];
    __shared__ const float* rowptr[BM];
    const int tid = threadIdx.x;
    const int rb = blockIdx.x * BM;
    const int n0 = blockIdx.y * BN;

    ull acc[2][8][2];   // f, o
#pragma unroll
    for (int j = 0; j < 2; j++)
#pragma unroll
        for (int r = 0; r < 8; r++) { acc[j][r][0] = 0ull; acc[j][r][1] = 0ull; }

    if (tid < BM) {
        int r = rb + tid;
        int node = nodeBase + (r >> 7);
        int b = r & 127;
        rowptr[tid] = g_h_buf + (size_t)((2 * node + 2) * BATCH + b) * MDIM;
    }
    __syncthreads();
    {
        const float* const Bp[2] = { Wsih + 256 + n0, Wsih + 768 + n0 };
        gemm8<2>(acc, rowptr, Bp, 1024, MDIM, sA, sB, tid);
    }
    __syncthreads();
    if (tid < BM) {
        int r = rb + tid;
        int node = nodeBase + (r >> 7);
        int b = r & 127;
        rowptr[tid] = rel + (size_t)(b * NNODES + 2 * node + 2) * RDIM;
    }
    __syncthreads();
    {
        const float* const Bp[2] = { Wsih + 256 * 1024 + 256 + n0, Wsih + 256 * 1024 + 768 + n0 };
        gemm8<2>(acc, rowptr, Bp, 1024, RDIM, sA, sB, tid);
    }
    __syncthreads();
    if (tid < BM) {
        int r = rb + tid;
        rowptr[tid] = g_h1 + (size_t)r * MDIM;
    }
    __syncthreads();
    {
        const float* const Bp[2] = { Wshh + 256 + n0, Wshh + 768 + n0 };
        gemm8<2>(acc, rowptr, Bp, 1024, MDIM, sA, sB, tid);
    }
    const int ty = tid >> 4, tx = tid & 15;
    const int m0 = n0 + tx * 4;
#pragma unroll
    for (int r8 = 0; r8 < 8; r8++) {
        int r = rb + ty * 8 + r8;
        size_t base = (size_t)r * MDIM + m0;
        float vf[4], vo[4];
        unp4(acc[0][r8], vf);
        unp4(acc[1][r8], vo);
        float4 c1v = *reinterpret_cast<const float4*>(&g_c1[base]);
        float4 igv = *reinterpret_cast<const float4*>(&g_ig[base]);
        float4 hv;
#pragma unroll
        for (int q = 0; q < 4; q++) {
            int m = m0 + q;
            float fv = sigf(vf[q] + bsi[256 + m] + bsh[256 + m]);
            float ov = sigf(vo[q] + bsi[768 + m] + bsh[768 + m]);
            float c2 = fv * (&c1v.x)[q] + (&igv.x)[q];
            (&hv.x)[q] = ov * tanhf(c2);
        }
        *reinterpret_cast<float4*>(&g_ht[base]) = hv;
    }
}

// ======================= Tree gates =======================
__global__ void __launch_bounds__(NTH, 2)
k_gates_iu(const float* __restrict__ wte,
           const float* __restrict__ Wix, const float* __restrict__ Wux,
           const float* __restrict__ Wih, const float* __restrict__ Wuh,
           const float* __restrict__ bix, const float* __restrict__ bih,
           const float* __restrict__ bux, const float* __restrict__ buh,
           int nodeBase)
{
    __shared__ __align__(16) float sA[2 * BK * SAS8];
    __shared__ __align__(16) float sB[2 * 2 * BK * BN];
    __shared__ const float* rowptr[BM];
    const int tid = threadIdx.x;
    const int rb = blockIdx.x * BM;
    const int n0 = blockIdx.y * BN;

    ull acc[2][8][2];
#pragma unroll
    for (int j = 0; j < 2; j++)
#pragma unroll
        for (int r = 0; r < 8; r++) { acc[j][r][0] = 0ull; acc[j][r][1] = 0ull; }

    if (tid < BM) {
        int r = rb + tid;
        int node = nodeBase + (r >> 7);
        int b = r & 127;
        rowptr[tid] = wte + (size_t)(b * NNODES + node) * INDIM;
    }
    __syncthreads();
    {
        const float* const Bp[2] = { Wix + n0, Wux + n0 };
        gemm8<2>(acc, rowptr, Bp, MDIM, INDIM, sA, sB, tid);
    }
    __syncthreads();
    if (tid < BM) {
        int r = rb + tid;
        rowptr[tid] = g_ht + (size_t)r * MDIM;
    }
    __syncthreads();
    {
        const float* const Bp[2] = { Wih + n0, Wuh + n0 };
        gemm8<2>(acc, rowptr, Bp, MDIM, MDIM, sA, sB, tid);
    }
    const int ty = tid >> 4, tx = tid & 15;
    const int m0 = n0 + tx * 4;
#pragma unroll
    for (int r8 = 0; r8 < 8; r8++) {
        int r = rb + ty * 8 + r8;
        size_t base = (size_t)r * MDIM + m0;
        float vi[4], vu[4];
        unp4(acc[0][r8], vi);
        unp4(acc[1][r8], vu);
        float4 cv;
#pragma unroll
        for (int q = 0; q < 4; q++) {
            int m = m0 + q;
            (&cv.x)[q] = sigf(vi[q] + bix[m] + bih[m]) * tanhf(vu[q] + bux[m] + buh[m]);
        }
        *reinterpret_cast<float4*>(&g_iu[base]) = cv;
    }
}

__global__ void __launch_bounds__(NTH, 2)
k_gates_ofx(const float* __restrict__ wte,
            const float* __restrict__ Wox, const float* __restrict__ Wfx,
            const float* __restrict__ Woh,
            const float* __restrict__ boxb, const float* __restrict__ boh,
            const float* __restrict__ bfx, const float* __restrict__ bfh,
            int nodeBase)
{
    __shared__ __align__(16) float sA[2 * BK * SAS8];
    __shared__ __align__(16) float sB[2 * 2 * BK * BN];
    __shared__ const float* rowptr[BM];
    const int tid = threadIdx.x;
    const int rb = blockIdx.x * BM;
    const int n0 = blockIdx.y * BN;

    ull acc[2][8][2];   // [0]=o, [1]=fx
#pragma unroll
    for (int j = 0; j < 2; j++)
#pragma unroll
        for (int r = 0; r < 8; r++) { acc[j][r][0] = 0ull; acc[j][r][1] = 0ull; }

    if (tid < BM) {
        int r = rb + tid;
        int node = nodeBase + (r >> 7);
        int b = r & 127;
        rowptr[tid] = wte + (size_t)(b * NNODES + node) * INDIM;
    }
    __syncthreads();
    {
        const float* const Bp[2] = { Wox + n0, Wfx + n0 };
        gemm8<2>(acc, rowptr, Bp, MDIM, INDIM, sA, sB, tid);
    }
    __syncthreads();
    if (tid < BM) {
        int r = rb + tid;
        rowptr[tid] = g_ht + (size_t)r * MDIM;
    }
    __syncthreads();
    {
        const float* const Bp[1] = { Woh + n0 };
        gemm8<1>(acc, rowptr, Bp, MDIM, MDIM, sA, sB, tid);   // o only
    }
    const int ty = tid >> 4, tx = tid & 15;
    const int m0 = n0 + tx * 4;
#pragma unroll
    for (int r8 = 0; r8 < 8; r8++) {
        int r = rb + ty * 8 + r8;
        size_t base = (size_t)r * MDIM + m0;
        float vo[4], vfx[4];
        unp4(acc[0][r8], vo);
        unp4(acc[1][r8], vfx);
        float4 ov, fv;
#pragma unroll
        for (int q = 0; q < 4; q++) {
            int m = m0 + q;
            (&ov.x)[q] = sigf(vo[q] + boxb[m] + boh[m]);
            (&fv.x)[q] = vfx[q] + bfx[m] + bfh[m];
        }
        *reinterpret_cast<float4*>(&g_og[base]) = ov;
        *reinterpret_cast<float4*>(&g_fx[base]) = fv;
    }
}

__global__ void __launch_bounds__(NTH, 2)
k_gates_f(const float* __restrict__ Wfh, int nodeBase, float* __restrict__ outp)
{
    __shared__ __align__(16) float sA0[2 * BK * SAS8];
    __shared__ __align__(16) float sA1[2 * BK * SAS8];
    __shared__ __align__(16) float sB[2 * 1 * BK * BN];
    __shared__ const float* rp0[BM];
    __shared__ const float* rp1[BM];
    const int tid = threadIdx.x;
    const int rb = blockIdx.x * BM;
    const int n0 = blockIdx.y * BN;

    ull acc[2][8][2];   // [0]=f0 delta, [1]=f1 delta
#pragma unroll
    for (int j = 0; j < 2; j++)
#pragma unroll
        for (int r = 0; r < 8; r++) { acc[j][r][0] = 0ull; acc[j][r][1] = 0ull; }

    if (tid < BM) {
        int r = rb + tid;
        int node = nodeBase + (r >> 7);
        int b = r & 127;
        rp0[tid] = g_h_buf + (size_t)((2 * node + 1) * BATCH + b) * MDIM;
        rp1[tid] = g_h_buf + (size_t)((2 * node + 2) * BATCH + b) * MDIM;
    }
    __syncthreads();
    gemm8_dual(acc, rp0, rp1, Wfh + n0, MDIM, MDIM, sA0, sA1, sB, tid);

    const int ty = tid >> 4, tx = tid & 15;
    const int m0 = n0 + tx * 4;
#pragma unroll
    for (int r8 = 0; r8 < 8; r8++) {
        int r = rb + ty * 8 + r8;
        int node = nodeBase + (r >> 7);
        int b = r & 127;
        size_t base  = (size_t)(node * BATCH + b) * MDIM + m0;
        size_t base0 = (size_t)((2 * node + 1) * BATCH + b) * MDIM + m0;
        size_t base1 = (size_t)((2 * node + 2) * BATCH + b) * MDIM + m0;
        size_t bs    = (size_t)r * MDIM + m0;
        float d0[4], d1[4];
        unp4(acc[0][r8], d0);
        unp4(acc[1][r8], d1);
        float4 fxv = *reinterpret_cast<const float4*>(&g_fx[bs]);
        float4 iuv = *reinterpret_cast<const float4*>(&g_iu[bs]);
        float4 ogv = *reinterpret_cast<const float4*>(&g_og[bs]);
        float4 cc0 = *reinterpret_cast<const float4*>(&g_c_buf[base0]);
        float4 cc1 = *reinterpret_cast<const float4*>(&g_c_buf[base1]);
        float4 hv, cv;
#pragma unroll
        for (int q = 0; q < 4; q++) {
            float f0 = sigf((&fxv.x)[q] + d0[q]);
            float f1 = sigf((&fxv.x)[q] + d1[q]);
            float c = (&iuv.x)[q] + f0 * (&cc0.x)[q] + f1 * (&cc1.x)[q];
            (&cv.x)[q] = c;
            (&hv.x)[q] = (&ogv.x)[q] * tanhf(c);
        }
        *reinterpret_cast<float4*>(&g_h_buf[base]) = hv;
        *reinterpret_cast<float4*>(&g_c_buf[base]) = cv;
        if (outp)
            *reinterpret_cast<float4*>(&outp[(size_t)r * MDIM + m0]) = hv;
    }
}

extern "C" void kernel_launch(void* const* d_in, const int* in_sizes, int n_in,
                              void* d_out, int out_size)
{
    const float* wte = nullptr;
    const float* rel = nullptr;
    const float* Wx[4];  int nWx = 0;   // ix, fx, ux, ox
    const float* Wh[4];  int nWh = 0;   // ih, fh, uh, oh
    const float* b256[8]; int nb = 0;   // bix,bfx,bux,box,bih,bfh,buh,boh
    const float* Wsih = nullptr;
    const float* Wshh = nullptr;
    const float* bseq[2]; int nbs = 0;  // b_seq_ih, b_seq_hh

    for (int i = 0; i < n_in; i++) {
        int s = in_sizes[i];
        const float* p = (const float*)d_in[i];
        switch (s) {
            case 33488896: wte = p; break;                 // 128*511*512
            case 4186112:  rel = p; break;                 // 128*511*64
            case 131072:   if (nWx < 4) Wx[nWx++] = p; break;   // 512*256
            case 65536:    if (nWh < 4) Wh[nWh++] = p; break;   // 256*256
            case 256:      if (nb < 8) b256[nb++] = p; break;
            case 327680:   Wsih = p; break;                // 320*1024
            case 262144:   Wshh = p; break;                // 256*1024
            case 1024:     if (nbs < 2) bseq[nbs++] = p; break;
            default: break;  // n_nodes (size 1): compile-time constant
        }
    }
    const float *Wix = Wx[0], *Wfx = Wx[1], *Wux = Wx[2], *Wox = Wx[3];
    const float *Wih = Wh[0], *Wfh = Wh[1], *Wuh = Wh[2], *Woh = Wh[3];
    const float *bix = b256[0], *bfx = b256[1], *bux = b256[2], *boxb = b256[3];
    const float *bih = b256[4], *bfh = b256[5], *buh = b256[6], *boh = b256[7];
    float* out = (float*)d_out;

    dim3 blk(NTH);

    // Leaves: 256 nodes = 32768 rows
    k_leaf_iu<<<dim3(256, 4), blk>>>(wte, Wix, Wux, bix, bih, bux, buh);
    k_leaf_o<<<dim3(256, 4), blk>>>(wte, Wox, boxb, boh);

    // Levels 7..0
    for (int L = 7; L >= 0; --L) {
        int P = 1 << L;
        int nodeBase = P - 1;
        dim3 grd(P, 4);
        k_cell1_ig<<<grd, blk>>>(rel, Wsih, bseq[0], bseq[1], nodeBase);
        k_cell1_o <<<grd, blk>>>(rel, Wsih, bseq[0], bseq[1], nodeBase);
        k_cell2_ig<<<grd, blk>>>(rel, Wsih, Wshh, bseq[0], bseq[1], nodeBase);
        k_cell2_fo<<<grd, blk>>>(rel, Wsih, Wshh, bseq[0], bseq[1], nodeBase);
        k_gates_iu<<<grd, blk>>>(wte, Wix, Wux, Wih, Wuh, bix, bih, bux, buh, nodeBase);
        k_gates_ofx<<<grd, blk>>>(wte, Wox, Wfx, Woh, boxb, boh, bfx, bfh, nodeBase);
        k_gates_f<<<grd, blk>>>(Wfh, nodeBase, (L == 0) ? out : nullptr);
    }
}